// round 1
// baseline (speedup 1.0000x reference)
#include <cuda_runtime.h>
#include <cuda_bf16.h>

#define N_NODES 50000
#define N_EDGES 800000
#define F 128

// ---------------- scratch (static device allocations; no cudaMalloc) ----------
__device__ int   g_count[N_NODES];       // in-degree (edges only)
__device__ int   g_fill[N_NODES];        // scatter cursors
__device__ int   g_rowptr[N_NODES + 1];  // CSR row pointers (by destination)
__device__ int   g_src[N_EDGES];         // CSR column indices = source nodes
__device__ float g_dinv[N_NODES];        // deg^{-1/2} (deg includes self-loop)
__device__ float g_h[(size_t)N_NODES * F];   // GEMM output buffer
__device__ float g_o[(size_t)N_NODES * F];   // aggregation output buffer (layer1)

// ---------------- zero counters ------------------------------------------------
__global__ void zero_kernel() {
    int i = blockIdx.x * blockDim.x + threadIdx.x;
    if (i < N_NODES) { g_count[i] = 0; g_fill[i] = 0; }
}

// ---------------- count in-degree by destination -------------------------------
__global__ void count_kernel(const int* __restrict__ col) {
    int stride = gridDim.x * blockDim.x;
    for (int e = blockIdx.x * blockDim.x + threadIdx.x; e < N_EDGES; e += stride)
        atomicAdd(&g_count[col[e]], 1);
}

// ---------------- single-block scan: rowptr (exclusive) + dinv -----------------
__global__ void scan_kernel() {
    __shared__ int warpsums[32];
    __shared__ int carry_s;
    const int tid  = threadIdx.x;           // 1024 threads
    const int lane = tid & 31;
    const int wid  = tid >> 5;
    if (tid == 0) carry_s = 0;
    __syncthreads();

    for (int base = 0; base < N_NODES; base += 1024) {
        int i = base + tid;
        int v = (i < N_NODES) ? g_count[i] : 0;
        if (i < N_NODES) g_dinv[i] = rsqrtf((float)(v + 1));  // +1 self loop
        int c = carry_s;

        // inclusive warp scan
        int x = v;
        #pragma unroll
        for (int o = 1; o < 32; o <<= 1) {
            int t = __shfl_up_sync(0xFFFFFFFFu, x, o);
            if (lane >= o) x += t;
        }
        if (lane == 31) warpsums[wid] = x;
        __syncthreads();
        if (wid == 0) {
            int w = warpsums[lane];
            #pragma unroll
            for (int o = 1; o < 32; o <<= 1) {
                int t = __shfl_up_sync(0xFFFFFFFFu, w, o);
                if (lane >= o) w += t;
            }
            warpsums[lane] = w;
        }
        __syncthreads();
        int wpre = (wid > 0) ? warpsums[wid - 1] : 0;
        int incl = x + wpre;
        if (i < N_NODES) g_rowptr[i] = c + incl - v;  // exclusive
        __syncthreads();
        if (tid == 1023) carry_s = c + incl;
        __syncthreads();
    }
    if (tid == 0) g_rowptr[N_NODES] = carry_s;  // == N_EDGES
}

// ---------------- scatter edges into CSR ---------------------------------------
__global__ void scatter_kernel(const int* __restrict__ row, const int* __restrict__ col) {
    int stride = gridDim.x * blockDim.x;
    for (int e = blockIdx.x * blockDim.x + threadIdx.x; e < N_EDGES; e += stride) {
        int c = col[e];
        int p = g_rowptr[c] + atomicAdd(&g_fill[c], 1);
        g_src[p] = row[e];
    }
}

// ---------------- GEMM: C[M,128] = A[M,128] @ W[128,128] -----------------------
// Block tile 128x128, 256 threads, 8x8 per-thread register tile, BK=8.
#define BM 128
#define BN 128
#define BK 8
#define TM 8
#define TN 8

__global__ __launch_bounds__(256, 2)
void gemm_kernel(const float* __restrict__ A, const float* __restrict__ W,
                 float* __restrict__ C, int M) {
    __shared__ float As[BK][BM];
    __shared__ float Bs[BK][BN];

    const int tid  = threadIdx.x;
    const int row0 = blockIdx.x * BM;
    const int tx   = tid & 15;   // 16 col-groups
    const int ty   = tid >> 4;   // 16 row-groups

    // A tile load mapping: thread -> (row = tid/2, kcol = (tid&1)*4), float4
    const int arow = tid >> 1;
    const int acol = (tid & 1) * 4;
    // W tile load mapping: thread -> (krow = tid/32, col = (tid&31)*4), float4
    const int brow = tid >> 5;
    const int bcol = (tid & 31) * 4;

    float acc[TM][TN];
    #pragma unroll
    for (int i = 0; i < TM; i++)
        #pragma unroll
        for (int j = 0; j < TN; j++) acc[i][j] = 0.0f;

    for (int k0 = 0; k0 < F; k0 += BK) {
        float4 av = make_float4(0.f, 0.f, 0.f, 0.f);
        int gr = row0 + arow;
        if (gr < M) av = *(const float4*)(A + (size_t)gr * F + k0 + acol);
        As[acol + 0][arow] = av.x;
        As[acol + 1][arow] = av.y;
        As[acol + 2][arow] = av.z;
        As[acol + 3][arow] = av.w;

        float4 bv = *(const float4*)(W + (size_t)(k0 + brow) * F + bcol);
        *(float4*)&Bs[brow][bcol] = bv;
        __syncthreads();

        #pragma unroll
        for (int kk = 0; kk < BK; kk++) {
            float a[TM], b[TN];
            float4 a0 = *(const float4*)&As[kk][ty * TM];
            float4 a1 = *(const float4*)&As[kk][ty * TM + 4];
            a[0]=a0.x; a[1]=a0.y; a[2]=a0.z; a[3]=a0.w;
            a[4]=a1.x; a[5]=a1.y; a[6]=a1.z; a[7]=a1.w;
            float4 b0 = *(const float4*)&Bs[kk][tx * TN];
            float4 b1 = *(const float4*)&Bs[kk][tx * TN + 4];
            b[0]=b0.x; b[1]=b0.y; b[2]=b0.z; b[3]=b0.w;
            b[4]=b1.x; b[5]=b1.y; b[6]=b1.z; b[7]=b1.w;
            #pragma unroll
            for (int i = 0; i < TM; i++)
                #pragma unroll
                for (int j = 0; j < TN; j++)
                    acc[i][j] = fmaf(a[i], b[j], acc[i][j]);
        }
        __syncthreads();
    }

    #pragma unroll
    for (int i = 0; i < TM; i++) {
        int r = row0 + ty * TM + i;
        if (r < M) {
            float4 o0 = make_float4(acc[i][0], acc[i][1], acc[i][2], acc[i][3]);
            float4 o1 = make_float4(acc[i][4], acc[i][5], acc[i][6], acc[i][7]);
            *(float4*)(C + (size_t)r * F + tx * TN)     = o0;
            *(float4*)(C + (size_t)r * F + tx * TN + 4) = o1;
        }
    }
}

// ---------------- aggregation: warp per destination node -----------------------
// out[d] = relu( dinv[d] * ( sum_e dinv[src_e]*h[src_e] + dinv[d]*h[d] ) + b )
__global__ __launch_bounds__(256)
void agg_kernel(const float* __restrict__ h, const float* __restrict__ bias,
                float* __restrict__ out) {
    int gwarp = (blockIdx.x * blockDim.x + threadIdx.x) >> 5;
    if (gwarp >= N_NODES) return;
    const int lane = threadIdx.x & 31;

    const int beg = g_rowptr[gwarp];
    const int end = g_rowptr[gwarp + 1];
    const float di = g_dinv[gwarp];

    const float4* __restrict__ h4 = (const float4*)h;

    // self loop: dinv[d]^2 * h[d]  ->  accumulate dinv[d]*h[d], multiply by di at end
    float4 v = h4[(size_t)gwarp * 32 + lane];
    float4 acc;
    acc.x = di * v.x; acc.y = di * v.y; acc.z = di * v.z; acc.w = di * v.w;

    int e = beg;
    // unrolled-by-2 to expose load-level parallelism
    for (; e + 1 < end; e += 2) {
        int s0 = g_src[e];
        int s1 = g_src[e + 1];
        float w0 = g_dinv[s0];
        float w1 = g_dinv[s1];
        float4 v0 = h4[(size_t)s0 * 32 + lane];
        float4 v1 = h4[(size_t)s1 * 32 + lane];
        acc.x = fmaf(w0, v0.x, acc.x); acc.y = fmaf(w0, v0.y, acc.y);
        acc.z = fmaf(w0, v0.z, acc.z); acc.w = fmaf(w0, v0.w, acc.w);
        acc.x = fmaf(w1, v1.x, acc.x); acc.y = fmaf(w1, v1.y, acc.y);
        acc.z = fmaf(w1, v1.z, acc.z); acc.w = fmaf(w1, v1.w, acc.w);
    }
    if (e < end) {
        int s0 = g_src[e];
        float w0 = g_dinv[s0];
        float4 v0 = h4[(size_t)s0 * 32 + lane];
        acc.x = fmaf(w0, v0.x, acc.x); acc.y = fmaf(w0, v0.y, acc.y);
        acc.z = fmaf(w0, v0.z, acc.z); acc.w = fmaf(w0, v0.w, acc.w);
    }

    float4 bb = ((const float4*)bias)[lane];
    float4 r;
    r.x = fmaxf(fmaf(di, acc.x, bb.x), 0.0f);
    r.y = fmaxf(fmaf(di, acc.y, bb.y), 0.0f);
    r.z = fmaxf(fmaf(di, acc.z, bb.z), 0.0f);
    r.w = fmaxf(fmaf(di, acc.w, bb.w), 0.0f);
    ((float4*)out)[(size_t)gwarp * 32 + lane] = r;
}

// ---------------- launch --------------------------------------------------------
extern "C" void kernel_launch(void* const* d_in, const int* in_sizes, int n_in,
                              void* d_out, int out_size) {
    const float* x    = (const float*)d_in[0];
    const int*   eidx = (const int*)d_in[1];   // [2, N_EDGES]
    const float* W1   = (const float*)d_in[2];
    const float* b1   = (const float*)d_in[3];
    const float* W2   = (const float*)d_in[4];
    const float* b2   = (const float*)d_in[5];
    float* out = (float*)d_out;

    const int* erow = eidx;             // source nodes
    const int* ecol = eidx + N_EDGES;   // target nodes

    float* h = nullptr;
    float* o = nullptr;
    cudaGetSymbolAddress((void**)&h, g_h);
    cudaGetSymbolAddress((void**)&o, g_o);

    // ---- build normalized CSR (by destination) ----
    zero_kernel<<<(N_NODES + 255) / 256, 256>>>();
    count_kernel<<<800, 512>>>(ecol);
    scan_kernel<<<1, 1024>>>();
    scatter_kernel<<<800, 512>>>(erow, ecol);

    const int gemm_blocks = (N_NODES + BM - 1) / BM;   // 391
    const int agg_blocks  = (N_NODES * 32 + 255) / 256; // warp per node, 8 warps/block

    // ---- layer 1 ----
    gemm_kernel<<<gemm_blocks, 256>>>(x, W1, h, N_NODES);
    agg_kernel<<<agg_blocks, 256>>>(h, b1, o);

    // ---- layer 2 ----
    gemm_kernel<<<gemm_blocks, 256>>>(o, W2, h, N_NODES);
    agg_kernel<<<agg_blocks, 256>>>(h, b2, out);
}

// round 3
// speedup vs baseline: 1.4747x; 1.4747x over previous
#include <cuda_runtime.h>
#include <cstdint>

#define N_NODES 50000
#define N_EDGES 800000
#define F 128
#define NBLK ((N_NODES + 255) / 256)   // 196

// ---------------- scratch (static device allocations; no cudaMalloc) ----------
__device__ int   g_count[N_NODES];
__device__ int   g_fill[N_NODES];
__device__ int   g_rowptr[N_NODES + 1];
__device__ int   g_src[N_EDGES];
__device__ float g_dinv[N_NODES];
__device__ int   g_bsum[NBLK];
__device__ int   g_boff[NBLK];
__device__ float g_whi[F * F];
__device__ float g_wlo[F * F];
__device__ float g_h[(size_t)N_NODES * F];
__device__ float g_o[(size_t)N_NODES * F];

// ================= helpers ======================================================
__device__ __forceinline__ uint32_t smem_to_u32(const void* p) {
    uint32_t a;
    asm("{ .reg .u64 t; cvta.to.shared.u64 t, %1; cvt.u32.u64 %0, t; }" : "=r"(a) : "l"(p));
    return a;
}
#define CP_ASYNC16(dst, src, sz) \
    asm volatile("cp.async.cg.shared.global [%0], [%1], 16, %2;" \
                 :: "r"(dst), "l"(src), "r"(sz) : "memory")
#define CP_COMMIT() asm volatile("cp.async.commit_group;" ::: "memory")
#define CP_WAIT(n)  asm volatile("cp.async.wait_group %0;" :: "n"(n) : "memory")

// m16n8k8 tf32 mma: a[4], b[2] are tf32 bit patterns in u32, c[4] fp32
__device__ __forceinline__ void mma_tf32(float* c, const uint32_t* a, const uint32_t* b) {
    asm volatile(
        "mma.sync.aligned.m16n8k8.row.col.f32.tf32.tf32.f32 "
        "{%0,%1,%2,%3}, {%4,%5,%6,%7}, {%8,%9}, {%0,%1,%2,%3};"
        : "+f"(c[0]), "+f"(c[1]), "+f"(c[2]), "+f"(c[3])
        : "r"(a[0]), "r"(a[1]), "r"(a[2]), "r"(a[3]), "r"(b[0]), "r"(b[1]));
}

// ---------------- CSR build kernels --------------------------------------------
__global__ void zero_kernel() {
    int i = blockIdx.x * blockDim.x + threadIdx.x;
    if (i < N_NODES) { g_count[i] = 0; g_fill[i] = 0; }
    if (i == 0) g_rowptr[N_NODES] = N_EDGES;
}

__global__ void count_kernel(const int* __restrict__ col) {
    int e = blockIdx.x * blockDim.x + threadIdx.x;
    if (e < N_EDGES) atomicAdd(&g_count[col[e]], 1);
}

__device__ __forceinline__ int block_incl_scan256(int v, int tid) {
    __shared__ int ws[8];
    const int lane = tid & 31, wid = tid >> 5;
    int x = v;
    #pragma unroll
    for (int o = 1; o < 32; o <<= 1) { int t = __shfl_up_sync(0xFFFFFFFFu, x, o); if (lane >= o) x += t; }
    if (lane == 31) ws[wid] = x;
    __syncthreads();
    if (wid == 0) {
        int w = (lane < 8) ? ws[lane] : 0;
        #pragma unroll
        for (int o = 1; o < 8; o <<= 1) { int t = __shfl_up_sync(0xFFFFFFFFu, w, o); if (lane >= o) w += t; }
        if (lane < 8) ws[lane] = w;
    }
    __syncthreads();
    return x + ((wid > 0) ? ws[wid - 1] : 0);
}

__global__ void blocksum_kernel() {
    __shared__ int ws[8];
    int tid = threadIdx.x;
    int i = blockIdx.x * 256 + tid;
    int v = (i < N_NODES) ? g_count[i] : 0;
    #pragma unroll
    for (int o = 16; o > 0; o >>= 1) v += __shfl_down_sync(0xFFFFFFFFu, v, o);
    if ((tid & 31) == 0) ws[tid >> 5] = v;
    __syncthreads();
    if (tid < 8) {
        int s = ws[tid];
        #pragma unroll
        for (int o = 4; o > 0; o >>= 1) s += __shfl_down_sync(0xFFu, s, o);
        if (tid == 0) g_bsum[blockIdx.x] = s;
    }
}

__global__ void scanoff_kernel() {
    int tid = threadIdx.x;
    int v = (tid < NBLK) ? g_bsum[tid] : 0;
    int incl = block_incl_scan256(v, tid);
    if (tid < NBLK) g_boff[tid] = incl - v;
}

__global__ void rowptr_kernel() {
    int tid = threadIdx.x;
    int i = blockIdx.x * 256 + tid;
    int v = (i < N_NODES) ? g_count[i] : 0;
    int incl = block_incl_scan256(v, tid);
    if (i < N_NODES) {
        g_rowptr[i] = g_boff[blockIdx.x] + incl - v;
        g_dinv[i] = rsqrtf((float)(v + 1));
    }
}

__global__ void scatter_kernel(const int* __restrict__ row, const int* __restrict__ col) {
    int e = blockIdx.x * blockDim.x + threadIdx.x;
    if (e < N_EDGES) {
        int c = col[e];
        int p = g_rowptr[c] + atomicAdd(&g_fill[c], 1);
        g_src[p] = row[e];
    }
}

// ---------------- W hi/lo split (tf32 3x decomposition) -------------------------
__global__ void wsplit_kernel(const float* __restrict__ W) {
    int i = blockIdx.x * blockDim.x + threadIdx.x;
    if (i < F * F) {
        float w = W[i];
        float hi = __uint_as_float(__float_as_uint(w) & 0xFFFFE000u);
        g_whi[i] = hi;
        g_wlo[i] = w - hi;
    }
}

// ---------------- tf32 3x GEMM: C[M,128] = A[M,128] @ W[128,128] ----------------
// CTA: 128 rows x 128 cols, 8 warps, warp = 32 rows x 64 cols.
// K in 4 chunks of 32, cp.async double buffer.
// SMEM floats per buffer: A[128][36] (4608) + Bh[32][136] (4352) + Bl (4352) = 13312
#define SM_A   0
#define SM_BH  4608
#define SM_BL  8960
#define SM_BUF 13312
#define SM_BYTES (2 * SM_BUF * 4)   // 106496

__device__ __forceinline__ void load_chunk(uint32_t sb, int buf,
        const float* __restrict__ A, int row0, int kc, int M, int tid) {
    const float* whi = g_whi;
    const float* wlo = g_wlo;
    uint32_t base = sb + (uint32_t)(buf * SM_BUF * 4);
    #pragma unroll
    for (int i = 0; i < 4; i++) {
        int t = tid + i * 256;
        int r = t >> 3, cc = t & 7;
        int gr = row0 + r;
        uint32_t sz = (gr < M) ? 16u : 0u;
        int grc = (gr < M) ? gr : 0;
        CP_ASYNC16(base + SM_A * 4 + (uint32_t)(r * 144 + cc * 16),
                   A + (size_t)grc * F + kc + cc * 4, sz);
    }
    #pragma unroll
    for (int i = 0; i < 4; i++) {
        int t = tid + i * 256;
        int r = t >> 5, cc = t & 31;
        const float* s1 = whi + (size_t)(kc + r) * F + cc * 4;
        const float* s2 = wlo + (size_t)(kc + r) * F + cc * 4;
        CP_ASYNC16(base + SM_BH * 4 + (uint32_t)(r * 544 + cc * 16), s1, 16u);
        CP_ASYNC16(base + SM_BL * 4 + (uint32_t)(r * 544 + cc * 16), s2, 16u);
    }
    CP_COMMIT();
}

__global__ __launch_bounds__(256, 2)
void gemm_kernel(const float* __restrict__ A, float* __restrict__ C, int M) {
    extern __shared__ float sm[];
    const uint32_t sb = smem_to_u32(sm);
    const int tid = threadIdx.x;
    const int wid = tid >> 5, lane = tid & 31;
    const int q = lane & 3, g = lane >> 2;
    const int wr = wid & 3, wc = wid >> 2;      // warp row/col group
    const int row0 = blockIdx.x * 128;

    float c[2][8][4];
    #pragma unroll
    for (int t = 0; t < 2; t++)
        #pragma unroll
        for (int j = 0; j < 8; j++)
            #pragma unroll
            for (int k = 0; k < 4; k++) c[t][j][k] = 0.0f;

    load_chunk(sb, 0, A, row0, 0, M, tid);

    #pragma unroll
    for (int ch = 0; ch < 4; ch++) {
        if (ch < 3) load_chunk(sb, (ch + 1) & 1, A, row0, (ch + 1) * 32, M, tid);
        if (ch < 3) { CP_WAIT(1); } else { CP_WAIT(0); }
        __syncthreads();

        const float* As = sm + (ch & 1) * SM_BUF + SM_A;
        const float* Bh = sm + (ch & 1) * SM_BUF + SM_BH;
        const float* Bl = sm + (ch & 1) * SM_BUF + SM_BL;

        #pragma unroll
        for (int kk = 0; kk < 4; kk++) {
            const int kb = kk * 8;
            uint32_t ahi[2][4], alo[2][4];
            #pragma unroll
            for (int t = 0; t < 2; t++) {
                int ar = wr * 32 + t * 16 + g;
                float a0 = As[ar * 36 + kb + q];
                float a1 = As[(ar + 8) * 36 + kb + q];
                float a2 = As[ar * 36 + kb + q + 4];
                float a3 = As[(ar + 8) * 36 + kb + q + 4];
                uint32_t h0 = __float_as_uint(a0) & 0xFFFFE000u;
                uint32_t h1 = __float_as_uint(a1) & 0xFFFFE000u;
                uint32_t h2 = __float_as_uint(a2) & 0xFFFFE000u;
                uint32_t h3 = __float_as_uint(a3) & 0xFFFFE000u;
                ahi[t][0] = h0; ahi[t][1] = h1; ahi[t][2] = h2; ahi[t][3] = h3;
                alo[t][0] = __float_as_uint(a0 - __uint_as_float(h0));
                alo[t][1] = __float_as_uint(a1 - __uint_as_float(h1));
                alo[t][2] = __float_as_uint(a2 - __uint_as_float(h2));
                alo[t][3] = __float_as_uint(a3 - __uint_as_float(h3));
            }
            #pragma unroll
            for (int j = 0; j < 8; j++) {
                int bc = wc * 64 + j * 8 + g;
                uint32_t bh[2], bl[2];
                bh[0] = __float_as_uint(Bh[(kb + q) * 136 + bc]);
                bh[1] = __float_as_uint(Bh[(kb + q + 4) * 136 + bc]);
                bl[0] = __float_as_uint(Bl[(kb + q) * 136 + bc]);
                bl[1] = __float_as_uint(Bl[(kb + q + 4) * 136 + bc]);
                #pragma unroll
                for (int t = 0; t < 2; t++) {
                    mma_tf32(c[t][j], ahi[t], bh);
                    mma_tf32(c[t][j], ahi[t], bl);
                    mma_tf32(c[t][j], alo[t], bh);
                }
            }
        }
        __syncthreads();
    }

    // epilogue: float2 stores
    #pragma unroll
    for (int t = 0; t < 2; t++) {
        int r0 = row0 + wr * 32 + t * 16 + g;
        #pragma unroll
        for (int j = 0; j < 8; j++) {
            int col = wc * 64 + j * 8 + 2 * q;
            if (r0 < M)
                *(float2*)(C + (size_t)r0 * F + col) = make_float2(c[t][j][0], c[t][j][1]);
            if (r0 + 8 < M)
                *(float2*)(C + (size_t)(r0 + 8) * F + col) = make_float2(c[t][j][2], c[t][j][3]);
        }
    }
}

// ---------------- aggregation: warp per destination node -----------------------
__global__ __launch_bounds__(256)
void agg_kernel(const float* __restrict__ h, const float* __restrict__ bias,
                float* __restrict__ out) {
    int gwarp = (blockIdx.x * blockDim.x + threadIdx.x) >> 5;
    if (gwarp >= N_NODES) return;
    const int lane = threadIdx.x & 31;

    const int beg = g_rowptr[gwarp];
    const int end = g_rowptr[gwarp + 1];
    const float di = g_dinv[gwarp];

    const float4* __restrict__ h4 = (const float4*)h;

    float4 v = h4[(size_t)gwarp * 32 + lane];
    float4 acc;
    acc.x = di * v.x; acc.y = di * v.y; acc.z = di * v.z; acc.w = di * v.w;

    int e = beg;
    for (; e + 1 < end; e += 2) {
        int s0 = g_src[e];
        int s1 = g_src[e + 1];
        float w0 = g_dinv[s0];
        float w1 = g_dinv[s1];
        float4 v0 = h4[(size_t)s0 * 32 + lane];
        float4 v1 = h4[(size_t)s1 * 32 + lane];
        acc.x = fmaf(w0, v0.x, acc.x); acc.y = fmaf(w0, v0.y, acc.y);
        acc.z = fmaf(w0, v0.z, acc.z); acc.w = fmaf(w0, v0.w, acc.w);
        acc.x = fmaf(w1, v1.x, acc.x); acc.y = fmaf(w1, v1.y, acc.y);
        acc.z = fmaf(w1, v1.z, acc.z); acc.w = fmaf(w1, v1.w, acc.w);
    }
    if (e < end) {
        int s0 = g_src[e];
        float w0 = g_dinv[s0];
        float4 v0 = h4[(size_t)s0 * 32 + lane];
        acc.x = fmaf(w0, v0.x, acc.x); acc.y = fmaf(w0, v0.y, acc.y);
        acc.z = fmaf(w0, v0.z, acc.z); acc.w = fmaf(w0, v0.w, acc.w);
    }

    float4 bb = ((const float4*)bias)[lane];
    float4 r;
    r.x = fmaxf(fmaf(di, acc.x, bb.x), 0.0f);
    r.y = fmaxf(fmaf(di, acc.y, bb.y), 0.0f);
    r.z = fmaxf(fmaf(di, acc.z, bb.z), 0.0f);
    r.w = fmaxf(fmaf(di, acc.w, bb.w), 0.0f);
    ((float4*)out)[(size_t)gwarp * 32 + lane] = r;
}

// ---------------- launch --------------------------------------------------------
extern "C" void kernel_launch(void* const* d_in, const int* in_sizes, int n_in,
                              void* d_out, int out_size) {
    const float* x    = (const float*)d_in[0];
    const int*   eidx = (const int*)d_in[1];
    const float* W1   = (const float*)d_in[2];
    const float* b1   = (const float*)d_in[3];
    const float* W2   = (const float*)d_in[4];
    const float* b2   = (const float*)d_in[5];
    float* out = (float*)d_out;

    const int* erow = eidx;
    const int* ecol = eidx + N_EDGES;

    float* h = nullptr;
    float* o = nullptr;
    cudaGetSymbolAddress((void**)&h, g_h);
    cudaGetSymbolAddress((void**)&o, g_o);

    cudaFuncSetAttribute(gemm_kernel, cudaFuncAttributeMaxDynamicSharedMemorySize, SM_BYTES);

    const int edge_blocks = (N_EDGES + 511) / 512;

    // ---- build normalized CSR (by destination) ----
    zero_kernel<<<(N_NODES + 255) / 256, 256>>>();
    count_kernel<<<edge_blocks, 512>>>(ecol);
    blocksum_kernel<<<NBLK, 256>>>();
    scanoff_kernel<<<1, 256>>>();
    rowptr_kernel<<<NBLK, 256>>>();
    scatter_kernel<<<edge_blocks, 512>>>(erow, ecol);

    const int gemm_blocks = (N_NODES + 127) / 128;     // 391
    const int agg_blocks  = (N_NODES * 32 + 255) / 256;

    // ---- layer 1 ----
    wsplit_kernel<<<(F * F + 255) / 256, 256>>>(W1);
    gemm_kernel<<<gemm_blocks, 256, SM_BYTES>>>(x, h, N_NODES);
    agg_kernel<<<agg_blocks, 256>>>(h, b1, o);

    // ---- layer 2 ----
    wsplit_kernel<<<(F * F + 255) / 256, 256>>>(W2);
    gemm_kernel<<<gemm_blocks, 256, SM_BYTES>>>(o, W2 ? h : h, N_NODES);
    agg_kernel<<<agg_blocks, 256>>>(h, b2, out);
}

// round 5
// speedup vs baseline: 1.5536x; 1.0535x over previous
#include <cuda_runtime.h>
#include <cstdint>

#define N_NODES 50000
#define N_EDGES 800000
#define F 128
#define NBLK ((N_NODES + 255) / 256)   // 196

// ---------------- scratch (static device allocations; no cudaMalloc) ----------
__device__ int   g_count[N_NODES];
__device__ int   g_fill[N_NODES];        // scatter cursors, init = rowptr
__device__ int   g_rowptr[N_NODES + 1];
__device__ int   g_src[N_EDGES];
__device__ float g_dinv[N_NODES];
__device__ int   g_bsum[NBLK];
__device__ float g_whi1[F * F];
__device__ float g_wlo1[F * F];
__device__ float g_whi2[F * F];
__device__ float g_wlo2[F * F];
__device__ float g_h[(size_t)N_NODES * F];
__device__ float g_o[(size_t)N_NODES * F];

// ================= helpers ======================================================
__device__ __forceinline__ uint32_t smem_to_u32(const void* p) {
    uint32_t a;
    asm("{ .reg .u64 t; cvta.to.shared.u64 t, %1; cvt.u32.u64 %0, t; }" : "=r"(a) : "l"(p));
    return a;
}
#define CP_ASYNC16(dst, src, sz) \
    asm volatile("cp.async.cg.shared.global [%0], [%1], 16, %2;" \
                 :: "r"(dst), "l"(src), "r"(sz) : "memory")
#define CP_COMMIT() asm volatile("cp.async.commit_group;" ::: "memory")
#define CP_WAIT(n)  asm volatile("cp.async.wait_group %0;" :: "n"(n) : "memory")

// m16n8k8 tf32 mma: a[4], b[2] are tf32 bit patterns in u32, c[4] fp32
__device__ __forceinline__ void mma_tf32(float* c, const uint32_t* a, const uint32_t* b) {
    asm volatile(
        "mma.sync.aligned.m16n8k8.row.col.f32.tf32.tf32.f32 "
        "{%0,%1,%2,%3}, {%4,%5,%6,%7}, {%8,%9}, {%0,%1,%2,%3};"
        : "+f"(c[0]), "+f"(c[1]), "+f"(c[2]), "+f"(c[3])
        : "r"(a[0]), "r"(a[1]), "r"(a[2]), "r"(a[3]), "r"(b[0]), "r"(b[1]));
}

// ---------------- CSR build kernels --------------------------------------------
__global__ void count_kernel(const int* __restrict__ col) {
    int e = blockIdx.x * blockDim.x + threadIdx.x;
    if (e < N_EDGES) atomicAdd(&g_count[col[e]], 1);
}

__global__ void blocksum_kernel() {
    __shared__ int ws[8];
    int tid = threadIdx.x;
    int i = blockIdx.x * 256 + tid;
    int v = (i < N_NODES) ? g_count[i] : 0;
    #pragma unroll
    for (int o = 16; o > 0; o >>= 1) v += __shfl_down_sync(0xFFFFFFFFu, v, o);
    if ((tid & 31) == 0) ws[tid >> 5] = v;
    __syncthreads();
    if (tid < 8) {
        int s = ws[tid];
        #pragma unroll
        for (int o = 4; o > 0; o >>= 1) s += __shfl_down_sync(0xFFu, s, o);
        if (tid == 0) g_bsum[blockIdx.x] = s;
    }
}

// rowptr + dinv + fill-cursor init; block offset computed by reducing g_bsum[0..bid)
__global__ void rowptr_kernel() {
    __shared__ int ws[8];
    __shared__ int s_off;
    const int tid = threadIdx.x, bid = blockIdx.x;
    const int lane = tid & 31, wid = tid >> 5;

    // ---- reduce g_bsum[0..bid) ----
    int r = (tid < bid) ? g_bsum[tid] : 0;
    #pragma unroll
    for (int o = 16; o > 0; o >>= 1) r += __shfl_down_sync(0xFFFFFFFFu, r, o);
    if (lane == 0) ws[wid] = r;
    __syncthreads();
    if (tid < 8) {
        int s = ws[tid];
        #pragma unroll
        for (int o = 4; o > 0; o >>= 1) s += __shfl_down_sync(0xFFu, s, o);
        if (tid == 0) s_off = s;
    }
    __syncthreads();

    // ---- block-local inclusive scan of counts ----
    int i = bid * 256 + tid;
    int v = (i < N_NODES) ? g_count[i] : 0;
    int x = v;
    #pragma unroll
    for (int o = 1; o < 32; o <<= 1) { int t = __shfl_up_sync(0xFFFFFFFFu, x, o); if (lane >= o) x += t; }
    if (lane == 31) ws[wid] = x;
    __syncthreads();
    if (wid == 0) {
        int w = (lane < 8) ? ws[lane] : 0;
        #pragma unroll
        for (int o = 1; o < 8; o <<= 1) { int t = __shfl_up_sync(0xFFFFFFFFu, w, o); if (lane >= o) w += t; }
        if (lane < 8) ws[lane] = w;
    }
    __syncthreads();
    int incl = x + ((wid > 0) ? ws[wid - 1] : 0);

    if (i < N_NODES) {
        int rp = s_off + incl - v;
        g_rowptr[i] = rp;
        g_fill[i]   = rp;
        g_dinv[i]   = rsqrtf((float)(v + 1));
    }
    if (bid == 0 && tid == 0) g_rowptr[N_NODES] = N_EDGES;
}

__global__ void scatter_kernel(const int* __restrict__ row, const int* __restrict__ col) {
    int e = blockIdx.x * blockDim.x + threadIdx.x;
    if (e < N_EDGES) {
        int p = atomicAdd(&g_fill[col[e]], 1);
        g_src[p] = row[e];
    }
}

// ---------------- W hi/lo split (tf32 3x decomposition) -------------------------
__global__ void wsplit_kernel(const float* __restrict__ W,
                              float* __restrict__ whi, float* __restrict__ wlo) {
    int i = blockIdx.x * blockDim.x + threadIdx.x;
    if (i < F * F) {
        float w = W[i];
        float hi = __uint_as_float(__float_as_uint(w) & 0xFFFFE000u);
        whi[i] = hi;
        wlo[i] = w - hi;
    }
}

// ---------------- tf32 3x GEMM: C[M,128] = A[M,128] @ W[128,128] ----------------
#define SM_A   0
#define SM_BH  4608
#define SM_BL  8960
#define SM_BUF 13312
#define SM_BYTES (2 * SM_BUF * 4)   // 106496

__device__ __forceinline__ void load_chunk(uint32_t sb, int buf,
        const float* __restrict__ A, const float* __restrict__ whi,
        const float* __restrict__ wlo, int row0, int kc, int M, int tid) {
    uint32_t base = sb + (uint32_t)(buf * SM_BUF * 4);
    #pragma unroll
    for (int i = 0; i < 4; i++) {
        int t = tid + i * 256;
        int r = t >> 3, cc = t & 7;
        int gr = row0 + r;
        uint32_t sz = (gr < M) ? 16u : 0u;
        int grc = (gr < M) ? gr : 0;
        CP_ASYNC16(base + SM_A * 4 + (uint32_t)(r * 144 + cc * 16),
                   A + (size_t)grc * F + kc + cc * 4, sz);
    }
    #pragma unroll
    for (int i = 0; i < 4; i++) {
        int t = tid + i * 256;
        int r = t >> 5, cc = t & 31;
        const float* s1 = whi + (size_t)(kc + r) * F + cc * 4;
        const float* s2 = wlo + (size_t)(kc + r) * F + cc * 4;
        CP_ASYNC16(base + SM_BH * 4 + (uint32_t)(r * 544 + cc * 16), s1, 16u);
        CP_ASYNC16(base + SM_BL * 4 + (uint32_t)(r * 544 + cc * 16), s2, 16u);
    }
    CP_COMMIT();
}

__global__ __launch_bounds__(256, 2)
void gemm_kernel(const float* __restrict__ A, const float* __restrict__ whi,
                 const float* __restrict__ wlo, float* __restrict__ C, int M) {
    extern __shared__ float sm[];
    const uint32_t sb = smem_to_u32(sm);
    const int tid = threadIdx.x;
    const int wid = tid >> 5, lane = tid & 31;
    const int q = lane & 3, g = lane >> 2;
    const int wr = wid & 3, wc = wid >> 2;
    const int row0 = blockIdx.x * 128;

    float c[2][8][4];
    #pragma unroll
    for (int t = 0; t < 2; t++)
        #pragma unroll
        for (int j = 0; j < 8; j++)
            #pragma unroll
            for (int k = 0; k < 4; k++) c[t][j][k] = 0.0f;

    load_chunk(sb, 0, A, whi, wlo, row0, 0, M, tid);

    #pragma unroll
    for (int ch = 0; ch < 4; ch++) {
        if (ch < 3) load_chunk(sb, (ch + 1) & 1, A, whi, wlo, row0, (ch + 1) * 32, M, tid);
        if (ch < 3) { CP_WAIT(1); } else { CP_WAIT(0); }
        __syncthreads();

        const float* As = sm + (ch & 1) * SM_BUF + SM_A;
        const float* Bh = sm + (ch & 1) * SM_BUF + SM_BH;
        const float* Bl = sm + (ch & 1) * SM_BUF + SM_BL;

        #pragma unroll
        for (int kk = 0; kk < 4; kk++) {
            const int kb = kk * 8;
            uint32_t ahi[2][4], alo[2][4];
            #pragma unroll
            for (int t = 0; t < 2; t++) {
                int ar = wr * 32 + t * 16 + g;
                float a0 = As[ar * 36 + kb + q];
                float a1 = As[(ar + 8) * 36 + kb + q];
                float a2 = As[ar * 36 + kb + q + 4];
                float a3 = As[(ar + 8) * 36 + kb + q + 4];
                uint32_t h0 = __float_as_uint(a0) & 0xFFFFE000u;
                uint32_t h1 = __float_as_uint(a1) & 0xFFFFE000u;
                uint32_t h2 = __float_as_uint(a2) & 0xFFFFE000u;
                uint32_t h3 = __float_as_uint(a3) & 0xFFFFE000u;
                ahi[t][0] = h0; ahi[t][1] = h1; ahi[t][2] = h2; ahi[t][3] = h3;
                alo[t][0] = __float_as_uint(a0 - __uint_as_float(h0));
                alo[t][1] = __float_as_uint(a1 - __uint_as_float(h1));
                alo[t][2] = __float_as_uint(a2 - __uint_as_float(h2));
                alo[t][3] = __float_as_uint(a3 - __uint_as_float(h3));
            }
            #pragma unroll
            for (int j = 0; j < 8; j++) {
                int bc = wc * 64 + j * 8 + g;
                uint32_t bh[2], bl[2];
                bh[0] = __float_as_uint(Bh[(kb + q) * 136 + bc]);
                bh[1] = __float_as_uint(Bh[(kb + q + 4) * 136 + bc]);
                bl[0] = __float_as_uint(Bl[(kb + q) * 136 + bc]);
                bl[1] = __float_as_uint(Bl[(kb + q + 4) * 136 + bc]);
                #pragma unroll
                for (int t = 0; t < 2; t++) {
                    mma_tf32(c[t][j], ahi[t], bh);
                    mma_tf32(c[t][j], ahi[t], bl);
                    mma_tf32(c[t][j], alo[t], bh);
                }
            }
        }
        __syncthreads();
    }

    #pragma unroll
    for (int t = 0; t < 2; t++) {
        int r0 = row0 + wr * 32 + t * 16 + g;
        #pragma unroll
        for (int j = 0; j < 8; j++) {
            int col = wc * 64 + j * 8 + 2 * q;
            if (r0 < M)
                *(float2*)(C + (size_t)r0 * F + col) = make_float2(c[t][j][0], c[t][j][1]);
            if (r0 + 8 < M)
                *(float2*)(C + (size_t)(r0 + 8) * F + col) = make_float2(c[t][j][2], c[t][j][3]);
        }
    }
}

// ---------------- aggregation: warp per destination node -----------------------
__global__ __launch_bounds__(256)
void agg_kernel(const float* __restrict__ h, const float* __restrict__ bias,
                float* __restrict__ out) {
    int gwarp = (blockIdx.x * blockDim.x + threadIdx.x) >> 5;
    if (gwarp >= N_NODES) return;
    const int lane = threadIdx.x & 31;

    const int beg = g_rowptr[gwarp];
    const int end = g_rowptr[gwarp + 1];
    const float di = g_dinv[gwarp];

    const float4* __restrict__ h4 = (const float4*)h;

    float4 v = h4[(size_t)gwarp * 32 + lane];
    float4 acc;
    acc.x = di * v.x; acc.y = di * v.y; acc.z = di * v.z; acc.w = di * v.w;

    int e = beg;
    for (; e + 1 < end; e += 2) {
        int s0 = g_src[e];
        int s1 = g_src[e + 1];
        float w0 = g_dinv[s0];
        float w1 = g_dinv[s1];
        float4 v0 = h4[(size_t)s0 * 32 + lane];
        float4 v1 = h4[(size_t)s1 * 32 + lane];
        acc.x = fmaf(w0, v0.x, acc.x); acc.y = fmaf(w0, v0.y, acc.y);
        acc.z = fmaf(w0, v0.z, acc.z); acc.w = fmaf(w0, v0.w, acc.w);
        acc.x = fmaf(w1, v1.x, acc.x); acc.y = fmaf(w1, v1.y, acc.y);
        acc.z = fmaf(w1, v1.z, acc.z); acc.w = fmaf(w1, v1.w, acc.w);
    }
    if (e < end) {
        int s0 = g_src[e];
        float w0 = g_dinv[s0];
        float4 v0 = h4[(size_t)s0 * 32 + lane];
        acc.x = fmaf(w0, v0.x, acc.x); acc.y = fmaf(w0, v0.y, acc.y);
        acc.z = fmaf(w0, v0.z, acc.z); acc.w = fmaf(w0, v0.w, acc.w);
    }

    float4 bb = ((const float4*)bias)[lane];
    float4 r;
    r.x = fmaxf(fmaf(di, acc.x, bb.x), 0.0f);
    r.y = fmaxf(fmaf(di, acc.y, bb.y), 0.0f);
    r.z = fmaxf(fmaf(di, acc.z, bb.z), 0.0f);
    r.w = fmaxf(fmaf(di, acc.w, bb.w), 0.0f);
    ((float4*)out)[(size_t)gwarp * 32 + lane] = r;
}

// ---------------- launch --------------------------------------------------------
extern "C" void kernel_launch(void* const* d_in, const int* in_sizes, int n_in,
                              void* d_out, int out_size) {
    const float* x    = (const float*)d_in[0];
    const int*   eidx = (const int*)d_in[1];
    const float* W1   = (const float*)d_in[2];
    const float* b1   = (const float*)d_in[3];
    const float* W2   = (const float*)d_in[4];
    const float* b2   = (const float*)d_in[5];
    float* out = (float*)d_out;

    const int* erow = eidx;
    const int* ecol = eidx + N_EDGES;

    float *h, *o, *whi1, *wlo1, *whi2, *wlo2;
    int *cnt;
    cudaGetSymbolAddress((void**)&h, g_h);
    cudaGetSymbolAddress((void**)&o, g_o);
    cudaGetSymbolAddress((void**)&whi1, g_whi1);
    cudaGetSymbolAddress((void**)&wlo1, g_wlo1);
    cudaGetSymbolAddress((void**)&whi2, g_whi2);
    cudaGetSymbolAddress((void**)&wlo2, g_wlo2);
    cudaGetSymbolAddress((void**)&cnt, g_count);

    cudaFuncSetAttribute(gemm_kernel, cudaFuncAttributeMaxDynamicSharedMemorySize, SM_BYTES);

    // Resources created ONCE, on the first (uncaptured correctness) call.
    // Nothing is created or destroyed while a capture is active.
    static cudaStream_t sE = []() {
        cudaStream_t s; cudaStreamCreateWithFlags(&s, cudaStreamNonBlocking); return s;
    }();
    static cudaEvent_t evRoot = []() {
        cudaEvent_t e; cudaEventCreateWithFlags(&e, cudaEventDisableTiming); return e;
    }();
    static cudaEvent_t evCsr = []() {
        cudaEvent_t e; cudaEventCreateWithFlags(&e, cudaEventDisableTiming); return e;
    }();

    const int edge_blocks = (N_EDGES + 511) / 512;
    const int gemm_blocks = (N_NODES + 127) / 128;
    const int agg_blocks  = (N_NODES * 32 + 255) / 256;

    // ---- fork ----
    cudaEventRecord(evRoot, 0);
    cudaStreamWaitEvent(sE, evRoot, 0);

    // side stream: CSR build + W2 split
    cudaMemsetAsync(cnt, 0, N_NODES * sizeof(int), sE);
    count_kernel<<<edge_blocks, 512, 0, sE>>>(ecol);
    blocksum_kernel<<<NBLK, 256, 0, sE>>>();
    rowptr_kernel<<<NBLK, 256, 0, sE>>>();
    scatter_kernel<<<edge_blocks, 512, 0, sE>>>(erow, ecol);
    wsplit_kernel<<<(F * F + 255) / 256, 256, 0, sE>>>(W2, whi2, wlo2);
    cudaEventRecord(evCsr, sE);

    // main stream: layer-1 GEMM concurrently with CSR build
    wsplit_kernel<<<(F * F + 255) / 256, 256>>>(W1, whi1, wlo1);
    gemm_kernel<<<gemm_blocks, 256, SM_BYTES>>>(x, whi1, wlo1, h, N_NODES);

    // ---- join, then the serial tail ----
    cudaStreamWaitEvent(0, evCsr, 0);
    agg_kernel<<<agg_blocks, 256>>>(h, b1, o);
    gemm_kernel<<<gemm_blocks, 256, SM_BYTES>>>(o, whi2, wlo2, h, N_NODES);
    agg_kernel<<<agg_blocks, 256>>>(h, b2, out);
}

// round 6
// speedup vs baseline: 1.6417x; 1.0567x over previous
#include <cuda_runtime.h>
#include <cuda_fp16.h>
#include <cstdint>

#define N_NODES 50000
#define N_EDGES 800000
#define F 128
#define NBLK ((N_NODES + 255) / 256)   // 196

// ---------------- scratch (static device allocations; no cudaMalloc) ----------
__device__ int    g_count[N_NODES];
__device__ int    g_fill[N_NODES];        // scatter cursors, init = rowptr
__device__ int    g_rowptr[N_NODES + 1];
__device__ int    g_src[N_EDGES];
__device__ float  g_dinv[N_NODES];
__device__ int    g_bsum[NBLK];
__device__ float  g_whi1[F * F];
__device__ float  g_wlo1[F * F];
__device__ float  g_whi2[F * F];
__device__ float  g_wlo2[F * F];
__device__ __half g_h[(size_t)N_NODES * F];   // GEMM output (fp16, gathered by agg)
__device__ float  g_o[(size_t)N_NODES * F];   // agg1 output (fp32, gemm2 input)

// ================= helpers ======================================================
__device__ __forceinline__ uint32_t smem_to_u32(const void* p) {
    uint32_t a;
    asm("{ .reg .u64 t; cvta.to.shared.u64 t, %1; cvt.u32.u64 %0, t; }" : "=r"(a) : "l"(p));
    return a;
}
#define CP_ASYNC16(dst, src, sz) \
    asm volatile("cp.async.cg.shared.global [%0], [%1], 16, %2;" \
                 :: "r"(dst), "l"(src), "r"(sz) : "memory")
#define CP_COMMIT() asm volatile("cp.async.commit_group;" ::: "memory")
#define CP_WAIT(n)  asm volatile("cp.async.wait_group %0;" :: "n"(n) : "memory")

__device__ __forceinline__ void mma_tf32(float* c, const uint32_t* a, const uint32_t* b) {
    asm volatile(
        "mma.sync.aligned.m16n8k8.row.col.f32.tf32.tf32.f32 "
        "{%0,%1,%2,%3}, {%4,%5,%6,%7}, {%8,%9}, {%0,%1,%2,%3};"
        : "+f"(c[0]), "+f"(c[1]), "+f"(c[2]), "+f"(c[3])
        : "r"(a[0]), "r"(a[1]), "r"(a[2]), "r"(a[3]), "r"(b[0]), "r"(b[1]));
}

// ---------------- CSR build kernels --------------------------------------------
__global__ void count_kernel(const int* __restrict__ col) {
    int e = blockIdx.x * blockDim.x + threadIdx.x;
    if (e < N_EDGES) atomicAdd(&g_count[col[e]], 1);
}

__global__ void blocksum_kernel() {
    __shared__ int ws[8];
    int tid = threadIdx.x;
    int i = blockIdx.x * 256 + tid;
    int v = (i < N_NODES) ? g_count[i] : 0;
    #pragma unroll
    for (int o = 16; o > 0; o >>= 1) v += __shfl_down_sync(0xFFFFFFFFu, v, o);
    if ((tid & 31) == 0) ws[tid >> 5] = v;
    __syncthreads();
    if (tid < 8) {
        int s = ws[tid];
        #pragma unroll
        for (int o = 4; o > 0; o >>= 1) s += __shfl_down_sync(0xFFu, s, o);
        if (tid == 0) g_bsum[blockIdx.x] = s;
    }
}

// rowptr + dinv + fill-cursor init; block offset = reduce g_bsum[0..bid)
__global__ void rowptr_kernel() {
    __shared__ int ws[8];
    __shared__ int s_off;
    const int tid = threadIdx.x, bid = blockIdx.x;
    const int lane = tid & 31, wid = tid >> 5;

    int r = (tid < bid) ? g_bsum[tid] : 0;
    #pragma unroll
    for (int o = 16; o > 0; o >>= 1) r += __shfl_down_sync(0xFFFFFFFFu, r, o);
    if (lane == 0) ws[wid] = r;
    __syncthreads();
    if (tid < 8) {
        int s = ws[tid];
        #pragma unroll
        for (int o = 4; o > 0; o >>= 1) s += __shfl_down_sync(0xFFu, s, o);
        if (tid == 0) s_off = s;
    }
    __syncthreads();

    int i = bid * 256 + tid;
    int v = (i < N_NODES) ? g_count[i] : 0;
    int x = v;
    #pragma unroll
    for (int o = 1; o < 32; o <<= 1) { int t = __shfl_up_sync(0xFFFFFFFFu, x, o); if (lane >= o) x += t; }
    if (lane == 31) ws[wid] = x;
    __syncthreads();
    if (wid == 0) {
        int w = (lane < 8) ? ws[lane] : 0;
        #pragma unroll
        for (int o = 1; o < 8; o <<= 1) { int t = __shfl_up_sync(0xFFFFFFFFu, w, o); if (lane >= o) w += t; }
        if (lane < 8) ws[lane] = w;
    }
    __syncthreads();
    int incl = x + ((wid > 0) ? ws[wid - 1] : 0);

    if (i < N_NODES) {
        int rp = s_off + incl - v;
        g_rowptr[i] = rp;
        g_fill[i]   = rp;
        g_dinv[i]   = rsqrtf((float)(v + 1));
    }
    if (bid == 0 && tid == 0) g_rowptr[N_NODES] = N_EDGES;
}

__global__ void scatter_kernel(const int* __restrict__ row, const int* __restrict__ col) {
    int e = blockIdx.x * blockDim.x + threadIdx.x;
    if (e < N_EDGES) {
        int p = atomicAdd(&g_fill[col[e]], 1);
        g_src[p] = row[e];
    }
}

// ---------------- W hi/lo split (tf32 3x decomposition) -------------------------
__global__ void wsplit_kernel(const float* __restrict__ W,
                              float* __restrict__ whi, float* __restrict__ wlo) {
    int i = blockIdx.x * blockDim.x + threadIdx.x;
    if (i < F * F) {
        float w = W[i];
        float hi = __uint_as_float(__float_as_uint(w) & 0xFFFFE000u);
        whi[i] = hi;
        wlo[i] = w - hi;
    }
}

// ---------------- tf32 3x GEMM: C[M,128](fp16) = A[M,128](fp32) @ W -------------
#define SM_A   0
#define SM_BH  4608
#define SM_BL  8960
#define SM_BUF 13312
#define SM_BYTES (2 * SM_BUF * 4)   // 106496

__device__ __forceinline__ void load_chunk(uint32_t sb, int buf,
        const float* __restrict__ A, const float* __restrict__ whi,
        const float* __restrict__ wlo, int row0, int kc, int M, int tid) {
    uint32_t base = sb + (uint32_t)(buf * SM_BUF * 4);
    #pragma unroll
    for (int i = 0; i < 4; i++) {
        int t = tid + i * 256;
        int r = t >> 3, cc = t & 7;
        int gr = row0 + r;
        uint32_t sz = (gr < M) ? 16u : 0u;
        int grc = (gr < M) ? gr : 0;
        CP_ASYNC16(base + SM_A * 4 + (uint32_t)(r * 144 + cc * 16),
                   A + (size_t)grc * F + kc + cc * 4, sz);
    }
    #pragma unroll
    for (int i = 0; i < 4; i++) {
        int t = tid + i * 256;
        int r = t >> 5, cc = t & 31;
        const float* s1 = whi + (size_t)(kc + r) * F + cc * 4;
        const float* s2 = wlo + (size_t)(kc + r) * F + cc * 4;
        CP_ASYNC16(base + SM_BH * 4 + (uint32_t)(r * 544 + cc * 16), s1, 16u);
        CP_ASYNC16(base + SM_BL * 4 + (uint32_t)(r * 544 + cc * 16), s2, 16u);
    }
    CP_COMMIT();
}

__global__ __launch_bounds__(256, 2)
void gemm_kernel(const float* __restrict__ A, const float* __restrict__ whi,
                 const float* __restrict__ wlo, __half* __restrict__ C, int M) {
    extern __shared__ float sm[];
    const uint32_t sb = smem_to_u32(sm);
    const int tid = threadIdx.x;
    const int wid = tid >> 5, lane = tid & 31;
    const int q = lane & 3, g = lane >> 2;
    const int wr = wid & 3, wc = wid >> 2;
    const int row0 = blockIdx.x * 128;

    float c[2][8][4];
    #pragma unroll
    for (int t = 0; t < 2; t++)
        #pragma unroll
        for (int j = 0; j < 8; j++)
            #pragma unroll
            for (int k = 0; k < 4; k++) c[t][j][k] = 0.0f;

    load_chunk(sb, 0, A, whi, wlo, row0, 0, M, tid);

    #pragma unroll
    for (int ch = 0; ch < 4; ch++) {
        if (ch < 3) load_chunk(sb, (ch + 1) & 1, A, whi, wlo, row0, (ch + 1) * 32, M, tid);
        if (ch < 3) { CP_WAIT(1); } else { CP_WAIT(0); }
        __syncthreads();

        const float* As = sm + (ch & 1) * SM_BUF + SM_A;
        const float* Bh = sm + (ch & 1) * SM_BUF + SM_BH;
        const float* Bl = sm + (ch & 1) * SM_BUF + SM_BL;

        #pragma unroll
        for (int kk = 0; kk < 4; kk++) {
            const int kb = kk * 8;
            uint32_t ahi[2][4], alo[2][4];
            #pragma unroll
            for (int t = 0; t < 2; t++) {
                int ar = wr * 32 + t * 16 + g;
                float a0 = As[ar * 36 + kb + q];
                float a1 = As[(ar + 8) * 36 + kb + q];
                float a2 = As[ar * 36 + kb + q + 4];
                float a3 = As[(ar + 8) * 36 + kb + q + 4];
                uint32_t h0 = __float_as_uint(a0) & 0xFFFFE000u;
                uint32_t h1 = __float_as_uint(a1) & 0xFFFFE000u;
                uint32_t h2 = __float_as_uint(a2) & 0xFFFFE000u;
                uint32_t h3 = __float_as_uint(a3) & 0xFFFFE000u;
                ahi[t][0] = h0; ahi[t][1] = h1; ahi[t][2] = h2; ahi[t][3] = h3;
                alo[t][0] = __float_as_uint(a0 - __uint_as_float(h0));
                alo[t][1] = __float_as_uint(a1 - __uint_as_float(h1));
                alo[t][2] = __float_as_uint(a2 - __uint_as_float(h2));
                alo[t][3] = __float_as_uint(a3 - __uint_as_float(h3));
            }
            #pragma unroll
            for (int j = 0; j < 8; j++) {
                int bc = wc * 64 + j * 8 + g;
                uint32_t bh[2], bl[2];
                bh[0] = __float_as_uint(Bh[(kb + q) * 136 + bc]);
                bh[1] = __float_as_uint(Bh[(kb + q + 4) * 136 + bc]);
                bl[0] = __float_as_uint(Bl[(kb + q) * 136 + bc]);
                bl[1] = __float_as_uint(Bl[(kb + q + 4) * 136 + bc]);
                #pragma unroll
                for (int t = 0; t < 2; t++) {
                    mma_tf32(c[t][j], ahi[t], bh);
                    mma_tf32(c[t][j], ahi[t], bl);
                    mma_tf32(c[t][j], alo[t], bh);
                }
            }
        }
        __syncthreads();
    }

    // epilogue: fp32 -> fp16, half2 stores
    #pragma unroll
    for (int t = 0; t < 2; t++) {
        int r0 = row0 + wr * 32 + t * 16 + g;
        #pragma unroll
        for (int j = 0; j < 8; j++) {
            int col = wc * 64 + j * 8 + 2 * q;
            if (r0 < M)
                *(__half2*)(C + (size_t)r0 * F + col) = __floats2half2_rn(c[t][j][0], c[t][j][1]);
            if (r0 + 8 < M)
                *(__half2*)(C + (size_t)(r0 + 8) * F + col) = __floats2half2_rn(c[t][j][2], c[t][j][3]);
        }
    }
}

// ---------------- aggregation: warp per destination node -----------------------
// h is fp16 (256B rows), accumulation fp32, output fp32.
__global__ __launch_bounds__(256)
void agg_kernel(const __half* __restrict__ h, const float* __restrict__ bias,
                float* __restrict__ out) {
    int gwarp = (blockIdx.x * blockDim.x + threadIdx.x) >> 5;
    if (gwarp >= N_NODES) return;
    const int lane = threadIdx.x & 31;

    const int beg = g_rowptr[gwarp];
    const int end = g_rowptr[gwarp + 1];
    const float di = g_dinv[gwarp];

    const uint2* __restrict__ h2 = (const uint2*)h;   // 4 halves per lane

    uint2 sv = h2[(size_t)gwarp * 32 + lane];
    float2 s01 = __half22float2(*(const __half2*)&sv.x);
    float2 s23 = __half22float2(*(const __half2*)&sv.y);
    float4 acc;
    acc.x = di * s01.x; acc.y = di * s01.y; acc.z = di * s23.x; acc.w = di * s23.y;

    int e = beg;
    for (; e + 1 < end; e += 2) {
        int s0 = g_src[e];
        int s1 = g_src[e + 1];
        float w0 = g_dinv[s0];
        float w1 = g_dinv[s1];
        uint2 v0 = h2[(size_t)s0 * 32 + lane];
        uint2 v1 = h2[(size_t)s1 * 32 + lane];
        float2 a01 = __half22float2(*(const __half2*)&v0.x);
        float2 a23 = __half22float2(*(const __half2*)&v0.y);
        float2 b01 = __half22float2(*(const __half2*)&v1.x);
        float2 b23 = __half22float2(*(const __half2*)&v1.y);
        acc.x = fmaf(w0, a01.x, acc.x); acc.y = fmaf(w0, a01.y, acc.y);
        acc.z = fmaf(w0, a23.x, acc.z); acc.w = fmaf(w0, a23.y, acc.w);
        acc.x = fmaf(w1, b01.x, acc.x); acc.y = fmaf(w1, b01.y, acc.y);
        acc.z = fmaf(w1, b23.x, acc.z); acc.w = fmaf(w1, b23.y, acc.w);
    }
    if (e < end) {
        int s0 = g_src[e];
        float w0 = g_dinv[s0];
        uint2 v0 = h2[(size_t)s0 * 32 + lane];
        float2 a01 = __half22float2(*(const __half2*)&v0.x);
        float2 a23 = __half22float2(*(const __half2*)&v0.y);
        acc.x = fmaf(w0, a01.x, acc.x); acc.y = fmaf(w0, a01.y, acc.y);
        acc.z = fmaf(w0, a23.x, acc.z); acc.w = fmaf(w0, a23.y, acc.w);
    }

    float4 bb = ((const float4*)bias)[lane];
    float4 r;
    r.x = fmaxf(fmaf(di, acc.x, bb.x), 0.0f);
    r.y = fmaxf(fmaf(di, acc.y, bb.y), 0.0f);
    r.z = fmaxf(fmaf(di, acc.z, bb.z), 0.0f);
    r.w = fmaxf(fmaf(di, acc.w, bb.w), 0.0f);
    ((float4*)out)[(size_t)gwarp * 32 + lane] = r;
}

// ---------------- launch --------------------------------------------------------
extern "C" void kernel_launch(void* const* d_in, const int* in_sizes, int n_in,
                              void* d_out, int out_size) {
    const float* x    = (const float*)d_in[0];
    const int*   eidx = (const int*)d_in[1];
    const float* W1   = (const float*)d_in[2];
    const float* b1   = (const float*)d_in[3];
    const float* W2   = (const float*)d_in[4];
    const float* b2   = (const float*)d_in[5];
    float* out = (float*)d_out;

    const int* erow = eidx;
    const int* ecol = eidx + N_EDGES;

    float *o, *whi1, *wlo1, *whi2, *wlo2;
    __half* h;
    int *cnt;
    cudaGetSymbolAddress((void**)&h, g_h);
    cudaGetSymbolAddress((void**)&o, g_o);
    cudaGetSymbolAddress((void**)&whi1, g_whi1);
    cudaGetSymbolAddress((void**)&wlo1, g_wlo1);
    cudaGetSymbolAddress((void**)&whi2, g_whi2);
    cudaGetSymbolAddress((void**)&wlo2, g_wlo2);
    cudaGetSymbolAddress((void**)&cnt, g_count);

    cudaFuncSetAttribute(gemm_kernel, cudaFuncAttributeMaxDynamicSharedMemorySize, SM_BYTES);

    // Resources created ONCE, on the first (uncaptured correctness) call.
    static cudaStream_t sE = []() {
        cudaStream_t s; cudaStreamCreateWithFlags(&s, cudaStreamNonBlocking); return s;
    }();
    static cudaEvent_t evRoot = []() {
        cudaEvent_t e; cudaEventCreateWithFlags(&e, cudaEventDisableTiming); return e;
    }();
    static cudaEvent_t evCsr = []() {
        cudaEvent_t e; cudaEventCreateWithFlags(&e, cudaEventDisableTiming); return e;
    }();

    const int edge_blocks = (N_EDGES + 511) / 512;
    const int gemm_blocks = (N_NODES + 127) / 128;
    const int agg_blocks  = (N_NODES * 32 + 255) / 256;

    // ---- fork ----
    cudaEventRecord(evRoot, 0);
    cudaStreamWaitEvent(sE, evRoot, 0);

    // side stream: CSR build + W2 split
    cudaMemsetAsync(cnt, 0, N_NODES * sizeof(int), sE);
    count_kernel<<<edge_blocks, 512, 0, sE>>>(ecol);
    blocksum_kernel<<<NBLK, 256, 0, sE>>>();
    rowptr_kernel<<<NBLK, 256, 0, sE>>>();
    scatter_kernel<<<edge_blocks, 512, 0, sE>>>(erow, ecol);
    wsplit_kernel<<<(F * F + 255) / 256, 256, 0, sE>>>(W2, whi2, wlo2);
    cudaEventRecord(evCsr, sE);

    // main stream: layer-1 GEMM concurrently with CSR build
    wsplit_kernel<<<(F * F + 255) / 256, 256>>>(W1, whi1, wlo1);
    gemm_kernel<<<gemm_blocks, 256, SM_BYTES>>>(x, whi1, wlo1, h, N_NODES);

    // ---- join, then the serial tail ----
    cudaStreamWaitEvent(0, evCsr, 0);
    agg_kernel<<<agg_blocks, 256>>>(h, b1, o);
    gemm_kernel<<<gemm_blocks, 256, SM_BYTES>>>(o, whi2, wlo2, h, N_NODES);
    agg_kernel<<<agg_blocks, 256>>>(h, b2, out);
}